// round 14
// baseline (speedup 1.0000x reference)
#include <cuda_runtime.h>
#include <cuda_bf16.h>
#include <cstdint>
#include <math.h>

// Problem constants (fixed shapes from setup_inputs)
#define BB 2
#define CC 64
#define LL 4096   // H*W = 64*64

// Scratch
__device__ float    g_F[(size_t)BB * LL * LL];          // fused scores, compact (nf x nuf), stride 4096
__device__ uint32_t g_Pbh32[(size_t)BB * LL * LL / 2];  // attn rows bf16 hi (packed pairs)
__device__ uint32_t g_Pbl32[(size_t)BB * LL * LL / 2];  // attn rows bf16 lo
__device__ uint32_t g_Fbh32[(size_t)BB * 64 * LL / 2];  // former bf16 hi
__device__ uint32_t g_Fbl32[(size_t)BB * 64 * LL / 2];  // former bf16 lo
__device__ uint32_t g_XTh[(size_t)BB * LL * 32];        // latter^T bf16 hi   [b][l][ch pairs]
__device__ uint32_t g_XTl[(size_t)BB * LL * 32];        // latter^T bf16 lo
__device__ uint32_t g_XNh[(size_t)BB * LL * 32];        // normalized latter^T bf16 hi
__device__ uint32_t g_XNl[(size_t)BB * LL * 32];        // normalized latter^T bf16 lo
// pre-gathered fused-GEMM operands, K = 9*64 = 576 => 288 uint32 per row
__device__ uint32_t g_Ah[(size_t)BB * LL * 288];
__device__ uint32_t g_Al[(size_t)BB * LL * 288];
__device__ uint32_t g_Bh[(size_t)BB * LL * 288];
__device__ uint32_t g_Bl[(size_t)BB * LL * 288];
__device__ float    g_part[(size_t)BB * 4 * LL * 64];   // K-split partials, 8 MiB
__device__ int      g_flag[LL];
__device__ int      g_list[LL];    // flagged l, compacted
__device__ int      g_ulist[LL];   // unflagged k, compacted
__device__ int      g_nflag;
__device__ int      g_nuflag;

// ---------------------------------------------------------------------------
// helpers
// ---------------------------------------------------------------------------
__device__ __forceinline__ uint32_t smem_u32(const void* p) {
    uint32_t a;
    asm("{ .reg .u64 t; cvta.to.shared.u64 t, %1; cvt.u32.u64 %0, t; }"
        : "=r"(a) : "l"(p));
    return a;
}
__device__ __forceinline__ void ldsm_x4(uint32_t* r, uint32_t addr) {
    asm volatile("ldmatrix.sync.aligned.m8n8.x4.shared.b16 {%0,%1,%2,%3}, [%4];"
                 : "=r"(r[0]), "=r"(r[1]), "=r"(r[2]), "=r"(r[3]) : "r"(addr));
}
__device__ __forceinline__ void mma_bf16(float* d, const uint32_t* a, const uint32_t* b) {
    asm volatile(
        "mma.sync.aligned.m16n8k16.row.col.f32.bf16.bf16.f32 "
        "{%0,%1,%2,%3}, {%4,%5,%6,%7}, {%8,%9}, {%0,%1,%2,%3};"
        : "+f"(d[0]), "+f"(d[1]), "+f"(d[2]), "+f"(d[3])
        : "r"(a[0]), "r"(a[1]), "r"(a[2]), "r"(a[3]), "r"(b[0]), "r"(b[1]));
}
#define SW128(o) ((o) ^ (((o) >> 3) & 0x70))

#define CP_ASYNC16(saddr, gptr) \
    asm volatile("cp.async.cg.shared.global [%0], [%1], 16;" \
                 :: "r"(saddr), "l"(gptr))
#define CP_COMMIT() asm volatile("cp.async.commit_group;")
#define CP_WAIT1()  asm volatile("cp.async.wait_group 1;")
#define CP_WAIT0()  asm volatile("cp.async.wait_group 0;")

__device__ __forceinline__ uint32_t pack_bf16_hi(float v0, float v1) {
    unsigned short h0 = __bfloat16_as_ushort(__float2bfloat16(v0));
    unsigned short h1 = __bfloat16_as_ushort(__float2bfloat16(v1));
    return (uint32_t)h0 | ((uint32_t)h1 << 16);
}
__device__ __forceinline__ uint32_t pack_bf16_lo(float v0, float v1, uint32_t hi) {
    float h0 = __bfloat162float(__ushort_as_bfloat16((unsigned short)(hi & 0xFFFF)));
    float h1 = __bfloat162float(__ushort_as_bfloat16((unsigned short)(hi >> 16)));
    unsigned short l0 = __bfloat16_as_ushort(__float2bfloat16(v0 - h0));
    unsigned short l1 = __bfloat16_as_ushort(__float2bfloat16(v1 - h1));
    return (uint32_t)l0 | ((uint32_t)l1 << 16);
}
__device__ __forceinline__ int tr_idx(int l) {   // flat transpose within 64x64
    return ((l & 63) << 6) | (l >> 6);
}

// ---------------------------------------------------------------------------
// Kernel 0: copy former+latter into out channels [0,128), zero shift [128,192)
// ---------------------------------------------------------------------------
__global__ void k_init_out(const float* __restrict__ x, float* __restrict__ out) {
    int idx = blockIdx.x * blockDim.x + threadIdx.x;
    const int total = BB * 192 * LL;
    if (idx >= total) return;
    int b  = idx / (192 * LL);
    int r  = idx - b * (192 * LL);
    int ch = r >> 12;
    int l  = r & (LL - 1);
    float v = 0.0f;
    if (ch < 128) v = x[((size_t)b * 128 + ch) * LL + l];
    out[idx] = v;
}

// ---------------------------------------------------------------------------
// Kernel 0b: convert former to bf16 hi/lo planes (packed pairs)
// ---------------------------------------------------------------------------
__global__ void k_fconv(const float* __restrict__ x) {
    int p = blockIdx.x * blockDim.x + threadIdx.x;
    const int total = BB * 64 * (LL / 2);
    if (p >= total) return;
    int b   = p / (64 * (LL / 2));
    int rem = p - b * (64 * (LL / 2));
    int ch  = rem / (LL / 2);
    int cp  = rem - ch * (LL / 2);
    const float* src = x + ((size_t)(b * 128 + ch)) * LL + cp * 2;
    float v0 = src[0], v1 = src[1];
    uint32_t hi = pack_bf16_hi(v0, v1);
    g_Fbh32[p] = hi;
    g_Fbl32[p] = pack_bf16_lo(v0, v1, hi);
}

// ---------------------------------------------------------------------------
// Kernel 1: per-(b,k): latter column -> XT hi/lo planes (raw + normalized),
// plus flags.
// ---------------------------------------------------------------------------
__global__ __launch_bounds__(256) void k_prep(const float* __restrict__ x,
                                              const float* __restrict__ mask) {
    int t = blockIdx.x * blockDim.x + threadIdx.x;
    if (t >= BB * LL) return;
    int b = t >> 12;
    int k = t & (LL - 1);
    const float* lat = x + ((size_t)b * 128 + 64) * LL;
    float v[CC];
    float s = 0.0f;
    #pragma unroll
    for (int c = 0; c < CC; c++) {
        v[c] = lat[(size_t)c * LL + k];
        s += v[c] * v[c];
    }
    float invn = 1.0f / fmaxf(sqrtf(s), 1e-4f);

    size_t base = (size_t)t * 32;
    #pragma unroll
    for (int p = 0; p < 32; p++) {
        float a0 = v[2 * p], a1 = v[2 * p + 1];
        uint32_t hi = pack_bf16_hi(a0, a1);
        g_XTh[base + p] = hi;
        g_XTl[base + p] = pack_bf16_lo(a0, a1, hi);
        float n0 = a0 * invn, n1 = a1 * invn;
        uint32_t nhi = pack_bf16_hi(n0, n1);
        g_XNh[base + p] = nhi;
        g_XNl[base + p] = pack_bf16_lo(n0, n1, nhi);
    }
    if (t < LL) g_flag[t] = (mask[t] > 0.5f) ? 1 : 0;
}

// ---------------------------------------------------------------------------
// Kernel 1b: deterministic compaction (warp-shfl scan, 2 barriers)
// ---------------------------------------------------------------------------
__global__ void k_compact() {
    __shared__ int wsum[8];
    int t = threadIdx.x;
    int lane = t & 31;
    int warp = t >> 5;
    int base_l = t * 16;
    int fl[16];
    #pragma unroll
    for (int q = 0; q < 4; q++) {
        int4 v = *(const int4*)&g_flag[base_l + q * 4];
        fl[q * 4 + 0] = v.x; fl[q * 4 + 1] = v.y;
        fl[q * 4 + 2] = v.z; fl[q * 4 + 3] = v.w;
    }
    int c = 0;
    #pragma unroll
    for (int j = 0; j < 16; j++) c += fl[j];
    int inc = c;
    #pragma unroll
    for (int off = 1; off < 32; off <<= 1) {
        int v = __shfl_up_sync(0xFFFFFFFFu, inc, off);
        if (lane >= off) inc += v;
    }
    if (lane == 31) wsum[warp] = inc;
    __syncthreads();
    if (t == 0) {
        int run = 0;
        #pragma unroll
        for (int i = 0; i < 8; i++) { int v = wsum[i]; wsum[i] = run; run += v; }
        g_nflag = run;
        g_nuflag = LL - run;
    }
    __syncthreads();
    int posF = wsum[warp] + inc - c;
    int posU = base_l - posF;
    #pragma unroll
    for (int j = 0; j < 16; j++) {
        int l = base_l + j;
        if (fl[j]) g_list[posF++] = l;
        else       g_ulist[posU++] = l;
    }
}

// ---------------------------------------------------------------------------
// Kernel 1c: build pre-gathered operands (zero-padded: A rows to 256,
// B rows to 128 — matching the fgemm tile sizes).
// ---------------------------------------------------------------------------
__global__ __launch_bounds__(256) void k_build() {
    int t = blockIdx.x * 256 + threadIdx.x;
    int chunk = t % 9;
    int rem   = t / 9;
    if (rem >= BB * 2 * LL) return;
    int row  = rem & (LL - 1);
    int side = (rem >> 12) & 1;
    int b    = rem >> 13;

    int nf = g_nflag, nuf = g_nuflag;
    int lim = side ? ((nuf + 127) & ~127) : ((nf + 255) & ~255);
    if (row >= lim) return;
    int n = side ? nuf : nf;

    int src = -1;
    if (row < n) {
        int l = side ? g_ulist[row] : g_list[row];
        int e = chunk / 3 - 1;
        int d = chunk % 3 - 1;
        int m2 = tr_idx(l) + e;
        if ((unsigned)m2 < (unsigned)LL) {
            int l2 = tr_idx(m2) + d;
            if ((unsigned)l2 < (unsigned)LL) src = l2;
        }
    }

    const uint4* sh = (const uint4*)(side ? g_XNh : g_XTh) + (size_t)b * LL * 8;
    const uint4* sl = (const uint4*)(side ? g_XNl : g_XTl) + (size_t)b * LL * 8;
    uint4* dh = (uint4*)(side ? g_Bh : g_Ah) + ((size_t)(b * LL + row) * 72 + chunk * 8);
    uint4* dl = (uint4*)(side ? g_Bl : g_Al) + ((size_t)(b * LL + row) * 72 + chunk * 8);
    uint4 z = make_uint4(0, 0, 0, 0);
    #pragma unroll
    for (int sec = 0; sec < 8; sec++) {
        dh[sec] = (src >= 0) ? sh[src * 8 + sec] : z;
        dl[sec] = (src >= 0) ? sl[src * 8 + sec] : z;
    }
}

// ---------------------------------------------------------------------------
// Kernel 2: pipelined fused score GEMM, LARGE WARP TILES (64x64).
// Block 256M x 128N, 8 warps (4 m-rows x 2 n-cols of 64x64 tiles).
// K = 9 chunks of 64, 2-stage cp.async (96 KB/stage, 192 KB smem, 1 CTA/SM).
// MAC/smem-byte doubles vs 32x32 tiles -> out of the LDSM-bandwidth wall.
// ---------------------------------------------------------------------------
#define ST_BYTES 98304
#define FA_H 0
#define FA_L 32768
#define FB_H 65536
#define FB_L 81920
#define F_DYN (2 * ST_BYTES)

__global__ __launch_bounds__(256, 1) void k_fgemm() {
    extern __shared__ char smem[];
    uint32_t sbase = smem_u32(smem);
    int tid = threadIdx.x;
    int j0 = blockIdx.x * 128;
    int i0 = blockIdx.y * 256;
    int b  = blockIdx.z;
    int nf = g_nflag, nuf = g_nuflag;
    if (i0 >= nf || j0 >= nuf) return;

    const uint4* Ah = (const uint4*)g_Ah;
    const uint4* Al = (const uint4*)g_Al;
    const uint4* Bh = (const uint4*)g_Bh;
    const uint4* Bl = (const uint4*)g_Bl;

    int wid  = tid >> 5;
    int lane = tid & 31;
    int wm = (wid & 3) * 64;    // 4 m-groups
    int wn = (wid >> 2) * 64;   // 2 n-groups
    int j  = lane & 7;
    int g  = lane >> 3;

    float acc[4][8][4];
    #pragma unroll
    for (int mi = 0; mi < 4; mi++)
        #pragma unroll
        for (int t = 0; t < 8; t++)
            #pragma unroll
            for (int q = 0; q < 4; q++) acc[mi][t][q] = 0.0f;

    int arow = tid >> 3, asec = tid & 7;
    uint32_t soff[8];
    #pragma unroll
    for (int it = 0; it < 8; it++)
        soff[it] = SW128((uint32_t)((arow + it * 32) * 128 + asec * 16));

    auto fill = [&](int c, int st) {
        uint32_t sb = sbase + st * ST_BYTES;
        #pragma unroll
        for (int it = 0; it < 8; it++) {   // A: 256 rows
            size_t gi = (size_t)(b * LL + i0 + arow + it * 32) * 72 + c * 8 + asec;
            CP_ASYNC16(sb + FA_H + soff[it], Ah + gi);
            CP_ASYNC16(sb + FA_L + soff[it], Al + gi);
        }
        #pragma unroll
        for (int it = 0; it < 4; it++) {   // B: 128 rows
            size_t gi = (size_t)(b * LL + j0 + arow + it * 32) * 72 + c * 8 + asec;
            CP_ASYNC16(sb + FB_H + soff[it], Bh + gi);
            CP_ASYNC16(sb + FB_L + soff[it], Bl + gi);
        }
    };

    fill(0, 0);
    CP_COMMIT();

    for (int c = 0; c < 9; c++) {
        if (c + 1 < 9) {
            fill(c + 1, (c + 1) & 1);
            CP_COMMIT();
            CP_WAIT1();
        } else {
            CP_WAIT0();
        }
        __syncthreads();

        uint32_t stb = sbase + (c & 1) * ST_BYTES;
        #pragma unroll
        for (int ksub = 0; ksub < 4; ksub++) {
            int kb = ksub * 32;
            uint32_t a_hi[4][4], a_lo[4][4], b_hi[4][4], b_lo[4][4];
            #pragma unroll
            for (int mi = 0; mi < 4; mi++) {
                uint32_t row = wm + mi * 16 + (g & 1) * 8 + j;
                uint32_t off = SW128(row * 128 + kb + (g >> 1) * 16);
                ldsm_x4(a_hi[mi], stb + FA_H + off);
                ldsm_x4(a_lo[mi], stb + FA_L + off);
            }
            #pragma unroll
            for (int tp = 0; tp < 4; tp++) {
                uint32_t row = wn + tp * 16 + (g >> 1) * 8 + j;
                uint32_t off = SW128(row * 128 + kb + (g & 1) * 16);
                ldsm_x4(b_hi[tp], stb + FB_H + off);
                ldsm_x4(b_lo[tp], stb + FB_L + off);
            }
            #pragma unroll
            for (int pass = 0; pass < 3; pass++) {
                #pragma unroll
                for (int mi = 0; mi < 4; mi++)
                    #pragma unroll
                    for (int t = 0; t < 8; t++) {
                        const uint32_t* ap = (pass == 2) ? a_lo[mi] : a_hi[mi];
                        const uint32_t* bp = (pass == 1)
                            ? &b_lo[t >> 1][(t & 1) * 2]
                            : &b_hi[t >> 1][(t & 1) * 2];
                        mma_bf16(acc[mi][t], ap, bp);
                    }
            }
        }
        __syncthreads();
    }

    float* Fp = g_F + ((size_t)b * LL + i0) * LL + j0;
    #pragma unroll
    for (int t = 0; t < 8; t++) {
        int n = wn + t * 8 + (lane & 3) * 2;
        #pragma unroll
        for (int mi = 0; mi < 4; mi++) {
            int r0 = wm + mi * 16 + (lane >> 2);
            *(float2*)&Fp[(size_t)r0 * LL + n] =
                make_float2(acc[mi][t][0], acc[mi][t][1]);
            *(float2*)&Fp[(size_t)(r0 + 8) * LL + n] =
                make_float2(acc[mi][t][2], acc[mi][t][3]);
        }
    }
}

// ---------------------------------------------------------------------------
// Kernel 3: softmax over compacted F rows -> P bf16 planes (full-width,
// zeros at flagged columns). fp32 __expf.
// ---------------------------------------------------------------------------
__global__ __launch_bounds__(256) void k_softmax2() {
    int ii = blockIdx.x;
    if (ii >= g_nflag) return;
    int b = blockIdx.y;
    int tid = threadIdx.x;
    int nuf = g_nuflag;

    __shared__ float row[LL];
    __shared__ float red[256];

    #pragma unroll
    for (int k = tid * 4; k < LL; k += 1024)
        *(float4*)&row[k] = make_float4(0.f, 0.f, 0.f, 0.f);

    const float* Fp = g_F + ((size_t)b * LL + ii) * LL;
    float v[16];
    int   uu[16];
    float mx = -INFINITY;
    #pragma unroll
    for (int i = 0; i < 16; i++) {
        int jj = tid + i * 256;
        if (jj < nuf) {
            v[i]  = Fp[jj];
            uu[i] = g_ulist[jj];
            mx = fmaxf(mx, v[i]);
        } else { v[i] = -INFINITY; uu[i] = 0; }
    }

    red[tid] = mx;
    __syncthreads();
    #pragma unroll
    for (int s = 128; s > 0; s >>= 1) {
        if (tid < s) red[tid] = fmaxf(red[tid], red[tid + s]);
        __syncthreads();
    }
    mx = red[0];
    __syncthreads();

    float sum = 0.0f;
    #pragma unroll
    for (int i = 0; i < 16; i++) {
        int jj = tid + i * 256;
        if (jj < nuf) {
            float e = __expf(v[i] - mx);
            v[i] = e;
            sum += e;
        }
    }
    red[tid] = sum;
    __syncthreads();
    #pragma unroll
    for (int s = 128; s > 0; s >>= 1) {
        if (tid < s) red[tid] += red[tid + s];
        __syncthreads();
    }
    float inv = 1.0f / red[0];
    __syncthreads();

    #pragma unroll
    for (int i = 0; i < 16; i++) {
        int jj = tid + i * 256;
        if (jj < nuf) row[uu[i]] = v[i] * inv;
    }
    __syncthreads();

    size_t base = ((size_t)b * LL + ii) * LL / 2;
    for (int kp = tid; kp < LL / 2; kp += 256) {
        float v0 = row[2 * kp];
        float v1 = row[2 * kp + 1];
        uint32_t hi = pack_bf16_hi(v0, v1);
        g_Pbh32[base + kp] = hi;
        g_Pbl32[base + kp] = pack_bf16_lo(v0, v1, hi);
    }
}

// ---------------------------------------------------------------------------
// Kernel 4a: shift GEMM stage 1 (tensor cores, K-split 4, partials).
// ---------------------------------------------------------------------------
#define SH_PH 0
#define SH_PL 8192
#define SH_FH 16384
#define SH_FL 24576

__global__ __launch_bounds__(256) void k_shift1() {
    __shared__ char smem[32768];
    uint32_t sbase = smem_u32(smem);

    int i0 = blockIdx.x * 64;
    int ks = blockIdx.y;
    int b  = blockIdx.z;
    if (i0 >= g_nflag) return;

    int tid  = threadIdx.x;
    int wid  = tid >> 5;
    int lane = tid & 31;
    int wm = (wid >> 1) * 16;
    int wn = (wid & 1) * 32;
    int j  = lane & 7;
    int g  = lane >> 3;

    float acc[4][4];
    #pragma unroll
    for (int t = 0; t < 4; t++)
        #pragma unroll
        for (int q = 0; q < 4; q++) acc[t][q] = 0.0f;

    for (int kc = 0; kc < 16; kc++) {
        int kb0 = ks * 1024 + kc * 64;
        __syncthreads();
        #pragma unroll
        for (int i = 0; i < 8; i++) {
            int e  = tid + i * 256;
            int r  = e >> 5;
            int cp = e & 31;
            size_t pidx = ((size_t)(b * LL + i0 + r) * LL + kb0) / 2 + cp;
            size_t fidx = ((size_t)(b * 64 + r) * LL + kb0) / 2 + cp;
            uint32_t off = SW128((uint32_t)(r * 128 + cp * 4));
            *(uint32_t*)(smem + SH_PH + off) = g_Pbh32[pidx];
            *(uint32_t*)(smem + SH_PL + off) = g_Pbl32[pidx];
            *(uint32_t*)(smem + SH_FH + off) = g_Fbh32[fidx];
            *(uint32_t*)(smem + SH_FL + off) = g_Fbl32[fidx];
        }
        __syncthreads();

        #pragma unroll
        for (int ksub = 0; ksub < 4; ksub++) {
            int kb = ksub * 32;
            uint32_t a_hi[4], a_lo[4], b_hi[2][4], b_lo[2][4];
            {
                uint32_t row = wm + (g & 1) * 8 + j;
                uint32_t off = SW128(row * 128 + kb + (g >> 1) * 16);
                ldsm_x4(a_hi, sbase + SH_PH + off);
                ldsm_x4(a_lo, sbase + SH_PL + off);
            }
            #pragma unroll
            for (int tp = 0; tp < 2; tp++) {
                uint32_t row = wn + tp * 16 + (g >> 1) * 8 + j;
                uint32_t off = SW128(row * 128 + kb + (g & 1) * 16);
                ldsm_x4(b_hi[tp], sbase + SH_FH + off);
                ldsm_x4(b_lo[tp], sbase + SH_FL + off);
            }
            #pragma unroll
            for (int pass = 0; pass < 3; pass++) {
                #pragma unroll
                for (int t = 0; t < 4; t++) {
                    const uint32_t* ap = (pass == 2) ? a_lo : a_hi;
                    const uint32_t* bp = (pass == 1)
                        ? &b_lo[t >> 1][(t & 1) * 2]
                        : &b_hi[t >> 1][(t & 1) * 2];
                    mma_bf16(acc[t], ap, bp);
                }
            }
        }
    }

    float* part = g_part + (size_t)(b * 4 + ks) * LL * 64;
    #pragma unroll
    for (int t = 0; t < 4; t++) {
        #pragma unroll
        for (int q = 0; q < 4; q++) {
            int row = wm + (lane >> 2) + ((q >= 2) ? 8 : 0);
            int ch  = wn + t * 8 + (lane & 3) * 2 + (q & 1);
            part[(size_t)(i0 + row) * 64 + ch] = acc[t][q];
        }
    }
}

// ---------------------------------------------------------------------------
// Kernel 4b: shift stage 2 — sum 4 K-split partials, scatter to out.
// ---------------------------------------------------------------------------
__global__ __launch_bounds__(256) void k_shift2(float* __restrict__ out) {
    int idx = blockIdx.x * 256 + threadIdx.x;
    int ch = idx & 63;
    int ii = (idx >> 6) & (LL - 1);
    int b  = idx >> 18;
    if (ii >= g_nflag) return;
    float s = 0.0f;
    #pragma unroll
    for (int ks = 0; ks < 4; ks++)
        s += g_part[(size_t)(b * 4 + ks) * LL * 64 + (size_t)ii * 64 + ch];
    int l = g_list[ii];
    out[((size_t)b * 192 + 128 + ch) * LL + l] = s;
}

// ---------------------------------------------------------------------------
extern "C" void kernel_launch(void* const* d_in, const int* in_sizes, int n_in,
                              void* d_out, int out_size) {
    const float* x    = (const float*)d_in[0];   // (2,128,64,64)
    const float* mask = (const float*)d_in[1];   // (1,1,64,64)
    float* out = (float*)d_out;                  // (2,192,64,64)

    {
        int total = BB * 192 * LL;
        k_init_out<<<(total + 255) / 256, 256>>>(x, out);
    }
    {
        int total = BB * 64 * (LL / 2);
        k_fconv<<<(total + 255) / 256, 256>>>(x);
    }
    {
        int total = BB * LL;
        k_prep<<<(total + 255) / 256, 256>>>(x, mask);
    }
    k_compact<<<1, 256>>>();
    {
        int total = BB * 2 * LL * 9;
        k_build<<<(total + 255) / 256, 256>>>();
    }
    {
        cudaFuncSetAttribute(k_fgemm, cudaFuncAttributeMaxDynamicSharedMemorySize, F_DYN);
        dim3 grid(LL / 128, LL / 256, BB);   // N-tiles x M-tiles x batch
        k_fgemm<<<grid, 256, F_DYN>>>();
    }
    {
        dim3 grid(LL, BB);
        k_softmax2<<<grid, 256>>>();
    }
    {
        dim3 grid(LL / 64, 4, BB);
        k_shift1<<<grid, 256>>>();
    }
    {
        int total = BB * LL * 64;
        k_shift2<<<total / 256, 256>>>(out);
    }
}

// round 15
// speedup vs baseline: 1.1442x; 1.1442x over previous
#include <cuda_runtime.h>
#include <cuda_bf16.h>
#include <cstdint>
#include <math.h>

// Problem constants (fixed shapes from setup_inputs)
#define BB 2
#define CC 64
#define LL 4096   // H*W = 64*64

// Scratch
__device__ float    g_S[(size_t)BB * LL * LL];          // score matrix, 128 MiB
__device__ uint32_t g_Pbh32[(size_t)BB * LL * LL / 2];  // attn rows bf16 hi (packed pairs)
__device__ uint32_t g_Pbl32[(size_t)BB * LL * LL / 2];  // attn rows bf16 lo
__device__ uint32_t g_Fbh32[(size_t)BB * 64 * LL / 2];  // former bf16 hi
__device__ uint32_t g_Fbl32[(size_t)BB * 64 * LL / 2];  // former bf16 lo
__device__ uint32_t g_XTh[(size_t)BB * LL * 32];        // latter^T bf16 hi  [b][l][ch pairs]
__device__ uint32_t g_XTl[(size_t)BB * LL * 32];        // latter^T bf16 lo
__device__ uint32_t g_XNh[(size_t)BB * LL * 32];        // normalized latter^T bf16 hi
__device__ uint32_t g_XNl[(size_t)BB * LL * 32];        // normalized latter^T bf16 lo
__device__ float    g_part[(size_t)BB * 4 * LL * 64];   // K-split partials, 8 MiB
__device__ int      g_flag[LL];
__device__ int      g_list[LL];
__device__ int      g_nflag;

// ---------------------------------------------------------------------------
// helpers
// ---------------------------------------------------------------------------
__device__ __forceinline__ uint32_t smem_u32(const void* p) {
    uint32_t a;
    asm("{ .reg .u64 t; cvta.to.shared.u64 t, %1; cvt.u32.u64 %0, t; }"
        : "=r"(a) : "l"(p));
    return a;
}
__device__ __forceinline__ void ldsm_x4(uint32_t* r, uint32_t addr) {
    asm volatile("ldmatrix.sync.aligned.m8n8.x4.shared.b16 {%0,%1,%2,%3}, [%4];"
                 : "=r"(r[0]), "=r"(r[1]), "=r"(r[2]), "=r"(r[3]) : "r"(addr));
}
__device__ __forceinline__ void mma_bf16(float* d, const uint32_t* a, const uint32_t* b) {
    asm volatile(
        "mma.sync.aligned.m16n8k16.row.col.f32.bf16.bf16.f32 "
        "{%0,%1,%2,%3}, {%4,%5,%6,%7}, {%8,%9}, {%0,%1,%2,%3};"
        : "+f"(d[0]), "+f"(d[1]), "+f"(d[2]), "+f"(d[3])
        : "r"(a[0]), "r"(a[1]), "r"(a[2]), "r"(a[3]), "r"(b[0]), "r"(b[1]));
}
#define SW128(o) ((o) ^ (((o) >> 3) & 0x70))

__device__ __forceinline__ uint32_t pack_bf16_hi(float v0, float v1) {
    unsigned short h0 = __bfloat16_as_ushort(__float2bfloat16(v0));
    unsigned short h1 = __bfloat16_as_ushort(__float2bfloat16(v1));
    return (uint32_t)h0 | ((uint32_t)h1 << 16);
}
__device__ __forceinline__ uint32_t pack_bf16_lo(float v0, float v1, uint32_t hi) {
    float h0 = __bfloat162float(__ushort_as_bfloat16((unsigned short)(hi & 0xFFFF)));
    float h1 = __bfloat162float(__ushort_as_bfloat16((unsigned short)(hi >> 16)));
    unsigned short l0 = __bfloat16_as_ushort(__float2bfloat16(v0 - h0));
    unsigned short l1 = __bfloat16_as_ushort(__float2bfloat16(v1 - h1));
    return (uint32_t)l0 | ((uint32_t)l1 << 16);
}

// ---------------------------------------------------------------------------
// Kernel 0: copy former+latter into out channels [0,128), zero shift [128,192)
// ---------------------------------------------------------------------------
__global__ void k_init_out(const float* __restrict__ x, float* __restrict__ out) {
    int idx = blockIdx.x * blockDim.x + threadIdx.x;
    const int total = BB * 192 * LL;
    if (idx >= total) return;
    int b  = idx / (192 * LL);
    int r  = idx - b * (192 * LL);
    int ch = r >> 12;
    int l  = r & (LL - 1);
    float v = 0.0f;
    if (ch < 128) v = x[((size_t)b * 128 + ch) * LL + l];
    out[idx] = v;
}

// ---------------------------------------------------------------------------
// Kernel 0b: convert former to bf16 hi/lo planes (packed pairs)
// ---------------------------------------------------------------------------
__global__ void k_fconv(const float* __restrict__ x) {
    int p = blockIdx.x * blockDim.x + threadIdx.x;
    const int total = BB * 64 * (LL / 2);
    if (p >= total) return;
    int b   = p / (64 * (LL / 2));
    int rem = p - b * (64 * (LL / 2));
    int ch  = rem / (LL / 2);
    int cp  = rem - ch * (LL / 2);
    const float* src = x + ((size_t)(b * 128 + ch)) * LL + cp * 2;
    float v0 = src[0], v1 = src[1];
    uint32_t hi = pack_bf16_hi(v0, v1);
    g_Fbh32[p] = hi;
    g_Fbl32[p] = pack_bf16_lo(v0, v1, hi);
}

// ---------------------------------------------------------------------------
// Kernel 1: per-(b,k): latter column -> XT hi/lo planes (raw + normalized),
// plus flags. ALL bf16 conversion happens here, once.
// ---------------------------------------------------------------------------
__global__ __launch_bounds__(256) void k_prep(const float* __restrict__ x,
                                              const float* __restrict__ mask) {
    int t = blockIdx.x * blockDim.x + threadIdx.x;
    if (t >= BB * LL) return;
    int b = t >> 12;
    int k = t & (LL - 1);
    const float* lat = x + ((size_t)b * 128 + 64) * LL;
    float v[CC];
    float s = 0.0f;
    #pragma unroll
    for (int c = 0; c < CC; c++) {
        v[c] = lat[(size_t)c * LL + k];
        s += v[c] * v[c];
    }
    float invn = 1.0f / fmaxf(sqrtf(s), 1e-4f);

    size_t base = (size_t)t * 32;
    #pragma unroll
    for (int p = 0; p < 32; p++) {
        float a0 = v[2 * p], a1 = v[2 * p + 1];
        uint32_t hi = pack_bf16_hi(a0, a1);
        g_XTh[base + p] = hi;
        g_XTl[base + p] = pack_bf16_lo(a0, a1, hi);
        float n0 = a0 * invn, n1 = a1 * invn;
        uint32_t nhi = pack_bf16_hi(n0, n1);
        g_XNh[base + p] = nhi;
        g_XNl[base + p] = pack_bf16_lo(n0, n1, nhi);
    }
    if (t < LL) g_flag[t] = (mask[t] > 0.5f) ? 1 : 0;
}

// ---------------------------------------------------------------------------
// Kernel 2: mma.sync bf16x3 score GEMM. Fill is PURE uint4 copies from the
// precomputed planes (no conversion); B side pre-normalized so the epilogue
// stores accumulators directly.
// ---------------------------------------------------------------------------
#define SM_AH 0
#define SM_AL 16384
#define SM_BH 32768
#define SM_BL 49152
#define SM_DYN 65536

__global__ __launch_bounds__(256) void k_gemm_mma() {
    extern __shared__ char smem[];
    uint32_t sbase = smem_u32(smem);
    int tid  = threadIdx.x;
    int n0 = blockIdx.x * 128;
    int m0 = blockIdx.y * 128;
    int b  = blockIdx.z;

    const uint4* XTh4 = (const uint4*)g_XTh + (size_t)b * LL * 2;
    const uint4* XTl4 = (const uint4*)g_XTl + (size_t)b * LL * 2;
    const uint4* XNh4 = (const uint4*)g_XNh + (size_t)b * LL * 2;
    const uint4* XNl4 = (const uint4*)g_XNl + (size_t)b * LL * 2;
    // each row l = 32 uint32 = 8 uint4 -> base index l*2... careful: 32 uint32
    // = 8 uint4, so row stride in uint4 is 8. Use explicit *8 indexing below.

    // ---- fill: 128 rows x 8 sectors per plane pair, pure 16B copies
    #pragma unroll
    for (int it = 0; it < 4; it++) {
        int task = tid + it * 256;
        int row = task >> 3, sec = task & 7;
        uint32_t off = SW128((uint32_t)(row * 128 + sec * 16));
        *(uint4*)(smem + SM_AH + off) = ((const uint4*)g_XTh)[((size_t)b * LL + m0 + row) * 8 + sec];
        *(uint4*)(smem + SM_AL + off) = ((const uint4*)g_XTl)[((size_t)b * LL + m0 + row) * 8 + sec];
        *(uint4*)(smem + SM_BH + off) = ((const uint4*)g_XNh)[((size_t)b * LL + n0 + row) * 8 + sec];
        *(uint4*)(smem + SM_BL + off) = ((const uint4*)g_XNl)[((size_t)b * LL + n0 + row) * 8 + sec];
    }
    (void)XTh4; (void)XTl4; (void)XNh4; (void)XNl4;
    __syncthreads();

    int wid  = tid >> 5;
    int lane = tid & 31;
    int wm = (wid & 3) * 32;
    int wn = (wid >> 2) * 64;
    int j  = lane & 7;
    int g  = lane >> 3;

    float acc[2][8][4];
    #pragma unroll
    for (int mi = 0; mi < 2; mi++)
        #pragma unroll
        for (int t = 0; t < 8; t++)
            #pragma unroll
            for (int q = 0; q < 4; q++) acc[mi][t][q] = 0.0f;

    #pragma unroll
    for (int kc = 0; kc < 4; kc++) {
        int kb = kc * 32;

        uint32_t a_hi[2][4], a_lo[2][4], b_hi[4][4], b_lo[4][4];
        #pragma unroll
        for (int mi = 0; mi < 2; mi++) {
            uint32_t row = wm + mi * 16 + (g & 1) * 8 + j;
            uint32_t kby = kb + (g >> 1) * 16;
            uint32_t off = SW128(row * 128 + kby);
            ldsm_x4(a_hi[mi], sbase + SM_AH + off);
            ldsm_x4(a_lo[mi], sbase + SM_AL + off);
        }
        #pragma unroll
        for (int tp = 0; tp < 4; tp++) {
            uint32_t row = wn + tp * 16 + (g >> 1) * 8 + j;
            uint32_t kby = kb + (g & 1) * 16;
            uint32_t off = SW128(row * 128 + kby);
            ldsm_x4(b_hi[tp], sbase + SM_BH + off);
            ldsm_x4(b_lo[tp], sbase + SM_BL + off);
        }

        #pragma unroll
        for (int mi = 0; mi < 2; mi++)
            #pragma unroll
            for (int t = 0; t < 8; t++) {
                const uint32_t* bh = &b_hi[t >> 1][(t & 1) * 2];
                const uint32_t* bl = &b_lo[t >> 1][(t & 1) * 2];
                mma_bf16(acc[mi][t], a_hi[mi], bh);
                mma_bf16(acc[mi][t], a_hi[mi], bl);
                mma_bf16(acc[mi][t], a_lo[mi], bh);
            }
    }

    float* Sp = g_S + (size_t)b * LL * LL;
    #pragma unroll
    for (int t = 0; t < 8; t++) {
        int n = wn + t * 8 + (lane & 3) * 2;
        #pragma unroll
        for (int mi = 0; mi < 2; mi++) {
            int r0 = m0 + wm + mi * 16 + (lane >> 2);
            *(float2*)&Sp[(size_t)r0 * LL + n0 + n] =
                make_float2(acc[mi][t][0], acc[mi][t][1]);
            *(float2*)&Sp[(size_t)(r0 + 8) * LL + n0 + n] =
                make_float2(acc[mi][t][2], acc[mi][t][3]);
        }
    }
}

// ---------------------------------------------------------------------------
// Kernel 1b: deterministic compaction (warp-shfl scan, 2 barriers)
// ---------------------------------------------------------------------------
__global__ void k_compact() {
    __shared__ int wsum[8];
    int t = threadIdx.x;
    int lane = t & 31;
    int warp = t >> 5;
    int base_l = t * 16;
    int fl[16];
    #pragma unroll
    for (int q = 0; q < 4; q++) {
        int4 v = *(const int4*)&g_flag[base_l + q * 4];
        fl[q * 4 + 0] = v.x; fl[q * 4 + 1] = v.y;
        fl[q * 4 + 2] = v.z; fl[q * 4 + 3] = v.w;
    }
    int c = 0;
    #pragma unroll
    for (int j = 0; j < 16; j++) c += fl[j];
    int inc = c;
    #pragma unroll
    for (int off = 1; off < 32; off <<= 1) {
        int v = __shfl_up_sync(0xFFFFFFFFu, inc, off);
        if (lane >= off) inc += v;
    }
    if (lane == 31) wsum[warp] = inc;
    __syncthreads();
    if (t == 0) {
        int run = 0;
        #pragma unroll
        for (int i = 0; i < 8; i++) { int v = wsum[i]; wsum[i] = run; run += v; }
        g_nflag = run;
    }
    __syncthreads();
    int posF = wsum[warp] + inc - c;
    #pragma unroll
    for (int j = 0; j < 16; j++) {
        int l = base_l + j;
        if (fl[j]) g_list[posF++] = l;
    }
}

// ---------------------------------------------------------------------------
// Kernel 3: per flagged row: 9-point fused gather, 4-wide vectorized + masked
// softmax (fp32 __expf); write normalized attn row as bf16 hi/lo planes.
// ---------------------------------------------------------------------------
__global__ __launch_bounds__(256) void k_softmax() {
    int ii = blockIdx.x;
    if (ii >= g_nflag) return;
    int l = g_list[ii];
    int b = blockIdx.y;

    __shared__ float row[LL];
    __shared__ float red[256];

    const float* S = g_S + (size_t)b * LL * LL;
    int tid = threadIdx.x;

    int hl = l >> 6, wl = l & 63;
    int ml = (wl << 6) | hl;

    const float* rp[3][3];
    bool rv[3][3];
    #pragma unroll
    for (int ei = 0; ei < 3; ei++) {
        int m2 = ml + ei - 1;
        bool v = (m2 >= 0 && m2 < LL);
        int l2v = v ? (((m2 & 63) << 6) | (m2 >> 6)) : 0;
        #pragma unroll
        for (int di = 0; di < 3; di++) {
            int r = l2v + di - 1;
            bool ok = v && (r >= 0 && r < LL);
            rv[ei][di] = ok;
            rp[ei][di] = ok ? (S + (size_t)r * LL) : S;
        }
    }

    float mx = -INFINITY;
    for (int idx = tid; idx < LL / 4; idx += 256) {
        int k0 = idx * 4;
        int h  = k0 >> 6;
        int w0 = k0 & 63;
        float a0 = 0.f, a1 = 0.f, a2 = 0.f, a3 = 0.f;

        #pragma unroll
        for (int ei = 0; ei < 3; ei++) {
            int hh = h + ei - 1;
            if (hh >= 0 && hh < 64) {
                int k2 = (hh << 6) | w0;
                #pragma unroll
                for (int di = 0; di < 3; di++) {
                    if (!rv[ei][di]) continue;
                    const float* rw = rp[ei][di];
                    float4 v = *(const float4*)&rw[k2];
                    if (di == 0) {
                        float vl = (k2 >= 1) ? rw[k2 - 1] : 0.0f;
                        a0 += vl;  a1 += v.x; a2 += v.y; a3 += v.z;
                    } else if (di == 1) {
                        a0 += v.x; a1 += v.y; a2 += v.z; a3 += v.w;
                    } else {
                        float vr = (k2 + 4 < LL) ? rw[k2 + 4] : 0.0f;
                        a0 += v.y; a1 += v.z; a2 += v.w; a3 += vr;
                    }
                }
            } else {
                bool neg = (hh < 0);
                float* accp[4] = {&a0, &a1, &a2, &a3};
                #pragma unroll
                for (int jj = 0; jj < 4; jj++) {
                    int w = w0 + jj;
                    int k2; bool kv;
                    if (neg) { k2 = 4032 + (w - 1); kv = (w >= 1); }
                    else     { k2 = w + 1;          kv = (w <= 62); }
                    if (!kv) continue;
                    #pragma unroll
                    for (int di = 0; di < 3; di++) {
                        int c = k2 + di - 1;
                        if (rv[ei][di] && c >= 0 && c < LL)
                            *accp[jj] += rp[ei][di][c];
                    }
                }
            }
        }

        int4 fl = *(const int4*)&g_flag[k0];
        float v0 = fl.x ? -INFINITY : a0;
        float v1 = fl.y ? -INFINITY : a1;
        float v2 = fl.z ? -INFINITY : a2;
        float v3 = fl.w ? -INFINITY : a3;
        *(float4*)&row[k0] = make_float4(v0, v1, v2, v3);
        mx = fmaxf(mx, fmaxf(fmaxf(v0, v1), fmaxf(v2, v3)));
    }

    red[tid] = mx;
    __syncthreads();
    #pragma unroll
    for (int s = 128; s > 0; s >>= 1) {
        if (tid < s) red[tid] = fmaxf(red[tid], red[tid + s]);
        __syncthreads();
    }
    mx = red[0];
    __syncthreads();

    float sum = 0.0f;
    for (int k = tid; k < LL; k += 256) {
        float v = row[k];
        float e = (v == -INFINITY) ? 0.0f : __expf(v - mx);
        row[k] = e;
        sum += e;
    }
    red[tid] = sum;
    __syncthreads();
    #pragma unroll
    for (int s = 128; s > 0; s >>= 1) {
        if (tid < s) red[tid] += red[tid + s];
        __syncthreads();
    }
    float inv = 1.0f / red[0];
    __syncthreads();

    size_t base = ((size_t)b * LL + ii) * LL / 2;
    for (int kp = tid; kp < LL / 2; kp += 256) {
        float v0 = row[2 * kp] * inv;
        float v1 = row[2 * kp + 1] * inv;
        uint32_t hi = pack_bf16_hi(v0, v1);
        g_Pbh32[base + kp] = hi;
        g_Pbl32[base + kp] = pack_bf16_lo(v0, v1, hi);
    }
}

// ---------------------------------------------------------------------------
// Kernel 4a: shift GEMM stage 1 (tensor cores, K-split 4, partials).
// ---------------------------------------------------------------------------
#define SH_PH 0
#define SH_PL 8192
#define SH_FH 16384
#define SH_FL 24576

__global__ __launch_bounds__(256) void k_shift1() {
    __shared__ char smem[32768];
    uint32_t sbase = smem_u32(smem);

    int i0 = blockIdx.x * 64;
    int ks = blockIdx.y;
    int b  = blockIdx.z;
    if (i0 >= g_nflag) return;

    int tid  = threadIdx.x;
    int wid  = tid >> 5;
    int lane = tid & 31;
    int wm = (wid >> 1) * 16;
    int wn = (wid & 1) * 32;
    int j  = lane & 7;
    int g  = lane >> 3;

    float acc[4][4];
    #pragma unroll
    for (int t = 0; t < 4; t++)
        #pragma unroll
        for (int q = 0; q < 4; q++) acc[t][q] = 0.0f;

    for (int kc = 0; kc < 16; kc++) {
        int kb0 = ks * 1024 + kc * 64;
        __syncthreads();
        #pragma unroll
        for (int i = 0; i < 8; i++) {
            int e  = tid + i * 256;
            int r  = e >> 5;
            int cp = e & 31;
            size_t pidx = ((size_t)(b * LL + i0 + r) * LL + kb0) / 2 + cp;
            size_t fidx = ((size_t)(b * 64 + r) * LL + kb0) / 2 + cp;
            uint32_t off = SW128((uint32_t)(r * 128 + cp * 4));
            *(uint32_t*)(smem + SH_PH + off) = g_Pbh32[pidx];
            *(uint32_t*)(smem + SH_PL + off) = g_Pbl32[pidx];
            *(uint32_t*)(smem + SH_FH + off) = g_Fbh32[fidx];
            *(uint32_t*)(smem + SH_FL + off) = g_Fbl32[fidx];
        }
        __syncthreads();

        #pragma unroll
        for (int ksub = 0; ksub < 4; ksub++) {
            int kb = ksub * 32;
            uint32_t a_hi[4], a_lo[4], b_hi[2][4], b_lo[2][4];
            {
                uint32_t row = wm + (g & 1) * 8 + j;
                uint32_t off = SW128(row * 128 + kb + (g >> 1) * 16);
                ldsm_x4(a_hi, sbase + SH_PH + off);
                ldsm_x4(a_lo, sbase + SH_PL + off);
            }
            #pragma unroll
            for (int tp = 0; tp < 2; tp++) {
                uint32_t row = wn + tp * 16 + (g >> 1) * 8 + j;
                uint32_t off = SW128(row * 128 + kb + (g & 1) * 16);
                ldsm_x4(b_hi[tp], sbase + SH_FH + off);
                ldsm_x4(b_lo[tp], sbase + SH_FL + off);
            }
            #pragma unroll
            for (int pass = 0; pass < 3; pass++) {
                #pragma unroll
                for (int t = 0; t < 4; t++) {
                    const uint32_t* ap = (pass == 2) ? a_lo : a_hi;
                    const uint32_t* bp = (pass == 1)
                        ? &b_lo[t >> 1][(t & 1) * 2]
                        : &b_hi[t >> 1][(t & 1) * 2];
                    mma_bf16(acc[t], ap, bp);
                }
            }
        }
    }

    float* part = g_part + (size_t)(b * 4 + ks) * LL * 64;
    #pragma unroll
    for (int t = 0; t < 4; t++) {
        #pragma unroll
        for (int q = 0; q < 4; q++) {
            int row = wm + (lane >> 2) + ((q >= 2) ? 8 : 0);
            int ch  = wn + t * 8 + (lane & 3) * 2 + (q & 1);
            part[(size_t)(i0 + row) * 64 + ch] = acc[t][q];
        }
    }
}

// ---------------------------------------------------------------------------
// Kernel 4b: shift stage 2 — sum 4 K-split partials, scatter to out.
// ---------------------------------------------------------------------------
__global__ __launch_bounds__(256) void k_shift2(float* __restrict__ out) {
    int idx = blockIdx.x * 256 + threadIdx.x;
    int ch = idx & 63;
    int ii = (idx >> 6) & (LL - 1);
    int b  = idx >> 18;
    if (ii >= g_nflag) return;
    float s = 0.0f;
    #pragma unroll
    for (int ks = 0; ks < 4; ks++)
        s += g_part[(size_t)(b * 4 + ks) * LL * 64 + (size_t)ii * 64 + ch];
    int l = g_list[ii];
    out[((size_t)b * 192 + 128 + ch) * LL + l] = s;
}

// ---------------------------------------------------------------------------
extern "C" void kernel_launch(void* const* d_in, const int* in_sizes, int n_in,
                              void* d_out, int out_size) {
    const float* x    = (const float*)d_in[0];   // (2,128,64,64)
    const float* mask = (const float*)d_in[1];   // (1,1,64,64)
    float* out = (float*)d_out;                  // (2,192,64,64)

    {
        int total = BB * 192 * LL;
        k_init_out<<<(total + 255) / 256, 256>>>(x, out);      // slot 0
    }
    {
        int total = BB * 64 * (LL / 2);
        k_fconv<<<(total + 255) / 256, 256>>>(x);              // slot 1
    }
    {
        int total = BB * LL;
        k_prep<<<(total + 255) / 256, 256>>>(x, mask);         // slot 2
    }
    {
        cudaFuncSetAttribute(k_gemm_mma, cudaFuncAttributeMaxDynamicSharedMemorySize, SM_DYN);
        dim3 grid(LL / 128, LL / 128, BB);
        k_gemm_mma<<<grid, 256, SM_DYN>>>();                   // slot 3 (profiled)
    }
    k_compact<<<1, 256>>>();                                   // slot 4
    {
        dim3 grid(LL, BB);
        k_softmax<<<grid, 256>>>();                            // slot 5
    }
    {
        dim3 grid(LL / 64, 4, BB);
        k_shift1<<<grid, 256>>>();                             // slot 6
    }
    {
        int total = BB * LL * 64;
        k_shift2<<<total / 256, 256>>>(out);                   // slot 7
    }
}

// round 16
// speedup vs baseline: 1.2696x; 1.1097x over previous
#include <cuda_runtime.h>
#include <cuda_bf16.h>
#include <cuda_fp16.h>
#include <cstdint>
#include <math.h>

// Problem constants (fixed shapes from setup_inputs)
#define BB 2
#define CC 64
#define LL 4096   // H*W = 64*64

// Scratch
__device__ __half   g_S[(size_t)BB * LL * LL];          // score matrix, fp16, 64 MiB
__device__ uint32_t g_Pbh32[(size_t)BB * LL * LL / 2];  // attn rows bf16 hi (packed pairs)
__device__ uint32_t g_Pbl32[(size_t)BB * LL * LL / 2];  // attn rows bf16 lo
__device__ uint32_t g_Fbh32[(size_t)BB * 64 * LL / 2];  // former bf16 hi
__device__ uint32_t g_Fbl32[(size_t)BB * 64 * LL / 2];  // former bf16 lo
__device__ uint32_t g_XTh[(size_t)BB * LL * 32];        // latter^T bf16 hi  [b][l][ch pairs]
__device__ uint32_t g_XTl[(size_t)BB * LL * 32];        // latter^T bf16 lo
__device__ uint32_t g_XNh[(size_t)BB * LL * 32];        // normalized latter^T bf16 hi
__device__ uint32_t g_XNl[(size_t)BB * LL * 32];        // normalized latter^T bf16 lo
__device__ float    g_part[(size_t)BB * 4 * LL * 64];   // K-split partials, 8 MiB
__device__ int      g_flag[LL];
__device__ int      g_list[LL];
__device__ int      g_nflag;

// ---------------------------------------------------------------------------
// helpers
// ---------------------------------------------------------------------------
__device__ __forceinline__ uint32_t smem_u32(const void* p) {
    uint32_t a;
    asm("{ .reg .u64 t; cvta.to.shared.u64 t, %1; cvt.u32.u64 %0, t; }"
        : "=r"(a) : "l"(p));
    return a;
}
__device__ __forceinline__ void ldsm_x4(uint32_t* r, uint32_t addr) {
    asm volatile("ldmatrix.sync.aligned.m8n8.x4.shared.b16 {%0,%1,%2,%3}, [%4];"
                 : "=r"(r[0]), "=r"(r[1]), "=r"(r[2]), "=r"(r[3]) : "r"(addr));
}
__device__ __forceinline__ void mma_bf16(float* d, const uint32_t* a, const uint32_t* b) {
    asm volatile(
        "mma.sync.aligned.m16n8k16.row.col.f32.bf16.bf16.f32 "
        "{%0,%1,%2,%3}, {%4,%5,%6,%7}, {%8,%9}, {%0,%1,%2,%3};"
        : "+f"(d[0]), "+f"(d[1]), "+f"(d[2]), "+f"(d[3])
        : "r"(a[0]), "r"(a[1]), "r"(a[2]), "r"(a[3]), "r"(b[0]), "r"(b[1]));
}
#define SW128(o) ((o) ^ (((o) >> 3) & 0x70))

__device__ __forceinline__ uint32_t pack_bf16_hi(float v0, float v1) {
    unsigned short h0 = __bfloat16_as_ushort(__float2bfloat16(v0));
    unsigned short h1 = __bfloat16_as_ushort(__float2bfloat16(v1));
    return (uint32_t)h0 | ((uint32_t)h1 << 16);
}
__device__ __forceinline__ uint32_t pack_bf16_lo(float v0, float v1, uint32_t hi) {
    float h0 = __bfloat162float(__ushort_as_bfloat16((unsigned short)(hi & 0xFFFF)));
    float h1 = __bfloat162float(__ushort_as_bfloat16((unsigned short)(hi >> 16)));
    unsigned short l0 = __bfloat16_as_ushort(__float2bfloat16(v0 - h0));
    unsigned short l1 = __bfloat16_as_ushort(__float2bfloat16(v1 - h1));
    return (uint32_t)l0 | ((uint32_t)l1 << 16);
}

// ---------------------------------------------------------------------------
// Kernel 0: copy former+latter into out channels [0,128), zero shift [128,192)
// ---------------------------------------------------------------------------
__global__ void k_init_out(const float* __restrict__ x, float* __restrict__ out) {
    int idx = blockIdx.x * blockDim.x + threadIdx.x;
    const int total = BB * 192 * LL;
    if (idx >= total) return;
    int b  = idx / (192 * LL);
    int r  = idx - b * (192 * LL);
    int ch = r >> 12;
    int l  = r & (LL - 1);
    float v = 0.0f;
    if (ch < 128) v = x[((size_t)b * 128 + ch) * LL + l];
    out[idx] = v;
}

// ---------------------------------------------------------------------------
// Kernel 0b: convert former to bf16 hi/lo planes (packed pairs)
// ---------------------------------------------------------------------------
__global__ void k_fconv(const float* __restrict__ x) {
    int p = blockIdx.x * blockDim.x + threadIdx.x;
    const int total = BB * 64 * (LL / 2);
    if (p >= total) return;
    int b   = p / (64 * (LL / 2));
    int rem = p - b * (64 * (LL / 2));
    int ch  = rem / (LL / 2);
    int cp  = rem - ch * (LL / 2);
    const float* src = x + ((size_t)(b * 128 + ch)) * LL + cp * 2;
    float v0 = src[0], v1 = src[1];
    uint32_t hi = pack_bf16_hi(v0, v1);
    g_Fbh32[p] = hi;
    g_Fbl32[p] = pack_bf16_lo(v0, v1, hi);
}

// ---------------------------------------------------------------------------
// Kernel 1: per-(b,k): latter column -> XT hi/lo planes (raw + normalized),
// plus flags. ALL bf16 conversion happens here, once.
// ---------------------------------------------------------------------------
__global__ __launch_bounds__(256) void k_prep(const float* __restrict__ x,
                                              const float* __restrict__ mask) {
    int t = blockIdx.x * blockDim.x + threadIdx.x;
    if (t >= BB * LL) return;
    int b = t >> 12;
    int k = t & (LL - 1);
    const float* lat = x + ((size_t)b * 128 + 64) * LL;
    float v[CC];
    float s = 0.0f;
    #pragma unroll
    for (int c = 0; c < CC; c++) {
        v[c] = lat[(size_t)c * LL + k];
        s += v[c] * v[c];
    }
    float invn = 1.0f / fmaxf(sqrtf(s), 1e-4f);

    size_t base = (size_t)t * 32;
    #pragma unroll
    for (int p = 0; p < 32; p++) {
        float a0 = v[2 * p], a1 = v[2 * p + 1];
        uint32_t hi = pack_bf16_hi(a0, a1);
        g_XTh[base + p] = hi;
        g_XTl[base + p] = pack_bf16_lo(a0, a1, hi);
        float n0 = a0 * invn, n1 = a1 * invn;
        uint32_t nhi = pack_bf16_hi(n0, n1);
        g_XNh[base + p] = nhi;
        g_XNl[base + p] = pack_bf16_lo(n0, n1, nhi);
    }
    if (t < LL) g_flag[t] = (mask[t] > 0.5f) ? 1 : 0;
}

// ---------------------------------------------------------------------------
// Kernel 2: mma.sync bf16x3 score GEMM. Pure uint4 fills from precomputed
// planes; fp16 S stores (halved write traffic).
// ---------------------------------------------------------------------------
#define SM_AH 0
#define SM_AL 16384
#define SM_BH 32768
#define SM_BL 49152
#define SM_DYN 65536

__global__ __launch_bounds__(256) void k_gemm_mma() {
    extern __shared__ char smem[];
    uint32_t sbase = smem_u32(smem);
    int tid  = threadIdx.x;
    int n0 = blockIdx.x * 128;
    int m0 = blockIdx.y * 128;
    int b  = blockIdx.z;

    // ---- fill: 128 rows x 8 sectors per plane pair, pure 16B copies
    #pragma unroll
    for (int it = 0; it < 4; it++) {
        int task = tid + it * 256;
        int row = task >> 3, sec = task & 7;
        uint32_t off = SW128((uint32_t)(row * 128 + sec * 16));
        *(uint4*)(smem + SM_AH + off) = ((const uint4*)g_XTh)[((size_t)b * LL + m0 + row) * 8 + sec];
        *(uint4*)(smem + SM_AL + off) = ((const uint4*)g_XTl)[((size_t)b * LL + m0 + row) * 8 + sec];
        *(uint4*)(smem + SM_BH + off) = ((const uint4*)g_XNh)[((size_t)b * LL + n0 + row) * 8 + sec];
        *(uint4*)(smem + SM_BL + off) = ((const uint4*)g_XNl)[((size_t)b * LL + n0 + row) * 8 + sec];
    }
    __syncthreads();

    int wid  = tid >> 5;
    int lane = tid & 31;
    int wm = (wid & 3) * 32;
    int wn = (wid >> 2) * 64;
    int j  = lane & 7;
    int g  = lane >> 3;

    float acc[2][8][4];
    #pragma unroll
    for (int mi = 0; mi < 2; mi++)
        #pragma unroll
        for (int t = 0; t < 8; t++)
            #pragma unroll
            for (int q = 0; q < 4; q++) acc[mi][t][q] = 0.0f;

    #pragma unroll
    for (int kc = 0; kc < 4; kc++) {
        int kb = kc * 32;

        uint32_t a_hi[2][4], a_lo[2][4], b_hi[4][4], b_lo[4][4];
        #pragma unroll
        for (int mi = 0; mi < 2; mi++) {
            uint32_t row = wm + mi * 16 + (g & 1) * 8 + j;
            uint32_t kby = kb + (g >> 1) * 16;
            uint32_t off = SW128(row * 128 + kby);
            ldsm_x4(a_hi[mi], sbase + SM_AH + off);
            ldsm_x4(a_lo[mi], sbase + SM_AL + off);
        }
        #pragma unroll
        for (int tp = 0; tp < 4; tp++) {
            uint32_t row = wn + tp * 16 + (g >> 1) * 8 + j;
            uint32_t kby = kb + (g & 1) * 16;
            uint32_t off = SW128(row * 128 + kby);
            ldsm_x4(b_hi[tp], sbase + SM_BH + off);
            ldsm_x4(b_lo[tp], sbase + SM_BL + off);
        }

        #pragma unroll
        for (int mi = 0; mi < 2; mi++)
            #pragma unroll
            for (int t = 0; t < 8; t++) {
                const uint32_t* bh = &b_hi[t >> 1][(t & 1) * 2];
                const uint32_t* bl = &b_lo[t >> 1][(t & 1) * 2];
                mma_bf16(acc[mi][t], a_hi[mi], bh);
                mma_bf16(acc[mi][t], a_hi[mi], bl);
                mma_bf16(acc[mi][t], a_lo[mi], bh);
            }
    }

    __half* Sp = g_S + (size_t)b * LL * LL;
    #pragma unroll
    for (int t = 0; t < 8; t++) {
        int n = wn + t * 8 + (lane & 3) * 2;
        #pragma unroll
        for (int mi = 0; mi < 2; mi++) {
            int r0 = m0 + wm + mi * 16 + (lane >> 2);
            __half2 p0 = __floats2half2_rn(acc[mi][t][0], acc[mi][t][1]);
            __half2 p1 = __floats2half2_rn(acc[mi][t][2], acc[mi][t][3]);
            *(__half2*)&Sp[(size_t)r0 * LL + n0 + n] = p0;
            *(__half2*)&Sp[(size_t)(r0 + 8) * LL + n0 + n] = p1;
        }
    }
}

// ---------------------------------------------------------------------------
// Kernel 1b: deterministic compaction (warp-shfl scan, 2 barriers)
// ---------------------------------------------------------------------------
__global__ void k_compact() {
    __shared__ int wsum[8];
    int t = threadIdx.x;
    int lane = t & 31;
    int warp = t >> 5;
    int base_l = t * 16;
    int fl[16];
    #pragma unroll
    for (int q = 0; q < 4; q++) {
        int4 v = *(const int4*)&g_flag[base_l + q * 4];
        fl[q * 4 + 0] = v.x; fl[q * 4 + 1] = v.y;
        fl[q * 4 + 2] = v.z; fl[q * 4 + 3] = v.w;
    }
    int c = 0;
    #pragma unroll
    for (int j = 0; j < 16; j++) c += fl[j];
    int inc = c;
    #pragma unroll
    for (int off = 1; off < 32; off <<= 1) {
        int v = __shfl_up_sync(0xFFFFFFFFu, inc, off);
        if (lane >= off) inc += v;
    }
    if (lane == 31) wsum[warp] = inc;
    __syncthreads();
    if (t == 0) {
        int run = 0;
        #pragma unroll
        for (int i = 0; i < 8; i++) { int v = wsum[i]; wsum[i] = run; run += v; }
        g_nflag = run;
    }
    __syncthreads();
    int posF = wsum[warp] + inc - c;
    #pragma unroll
    for (int j = 0; j < 16; j++) {
        int l = base_l + j;
        if (fl[j]) g_list[posF++] = l;
    }
}

// ---------------------------------------------------------------------------
// Kernel 3: per flagged row: 9-point fused gather (fp16 S, 4-wide) + masked
// softmax (fp32 __expf); write normalized attn row as bf16 hi/lo planes.
// ---------------------------------------------------------------------------
__global__ __launch_bounds__(256) void k_softmax() {
    int ii = blockIdx.x;
    if (ii >= g_nflag) return;
    int l = g_list[ii];
    int b = blockIdx.y;

    __shared__ float row[LL];
    __shared__ float red[256];

    const __half* S = g_S + (size_t)b * LL * LL;
    int tid = threadIdx.x;

    int hl = l >> 6, wl = l & 63;
    int ml = (wl << 6) | hl;

    const __half* rp[3][3];
    bool rv[3][3];
    #pragma unroll
    for (int ei = 0; ei < 3; ei++) {
        int m2 = ml + ei - 1;
        bool v = (m2 >= 0 && m2 < LL);
        int l2v = v ? (((m2 & 63) << 6) | (m2 >> 6)) : 0;
        #pragma unroll
        for (int di = 0; di < 3; di++) {
            int r = l2v + di - 1;
            bool ok = v && (r >= 0 && r < LL);
            rv[ei][di] = ok;
            rp[ei][di] = ok ? (S + (size_t)r * LL) : S;
        }
    }

    float mx = -INFINITY;
    for (int idx = tid; idx < LL / 4; idx += 256) {
        int k0 = idx * 4;
        int h  = k0 >> 6;
        int w0 = k0 & 63;
        float a0 = 0.f, a1 = 0.f, a2 = 0.f, a3 = 0.f;

        #pragma unroll
        for (int ei = 0; ei < 3; ei++) {
            int hh = h + ei - 1;
            if (hh >= 0 && hh < 64) {
                int k2 = (hh << 6) | w0;
                #pragma unroll
                for (int di = 0; di < 3; di++) {
                    if (!rv[ei][di]) continue;
                    const __half* rw = rp[ei][di];
                    uint2 raw = *(const uint2*)&rw[k2];   // half4, 8B aligned
                    float2 f01 = __half22float2(*(__half2*)&raw.x);
                    float2 f23 = __half22float2(*(__half2*)&raw.y);
                    if (di == 0) {
                        float vl = (k2 >= 1) ? __half2float(rw[k2 - 1]) : 0.0f;
                        a0 += vl;    a1 += f01.x; a2 += f01.y; a3 += f23.x;
                    } else if (di == 1) {
                        a0 += f01.x; a1 += f01.y; a2 += f23.x; a3 += f23.y;
                    } else {
                        float vr = (k2 + 4 < LL) ? __half2float(rw[k2 + 4]) : 0.0f;
                        a0 += f01.y; a1 += f23.x; a2 += f23.y; a3 += vr;
                    }
                }
            } else {
                bool neg = (hh < 0);
                float* accp[4] = {&a0, &a1, &a2, &a3};
                #pragma unroll
                for (int jj = 0; jj < 4; jj++) {
                    int w = w0 + jj;
                    int k2; bool kv;
                    if (neg) { k2 = 4032 + (w - 1); kv = (w >= 1); }
                    else     { k2 = w + 1;          kv = (w <= 62); }
                    if (!kv) continue;
                    #pragma unroll
                    for (int di = 0; di < 3; di++) {
                        int c = k2 + di - 1;
                        if (rv[ei][di] && c >= 0 && c < LL)
                            *accp[jj] += __half2float(rp[ei][di][c]);
                    }
                }
            }
        }

        int4 fl = *(const int4*)&g_flag[k0];
        float v0 = fl.x ? -INFINITY : a0;
        float v1 = fl.y ? -INFINITY : a1;
        float v2 = fl.z ? -INFINITY : a2;
        float v3 = fl.w ? -INFINITY : a3;
        *(float4*)&row[k0] = make_float4(v0, v1, v2, v3);
        mx = fmaxf(mx, fmaxf(fmaxf(v0, v1), fmaxf(v2, v3)));
    }

    red[tid] = mx;
    __syncthreads();
    #pragma unroll
    for (int s = 128; s > 0; s >>= 1) {
        if (tid < s) red[tid] = fmaxf(red[tid], red[tid + s]);
        __syncthreads();
    }
    mx = red[0];
    __syncthreads();

    float sum = 0.0f;
    for (int k = tid; k < LL; k += 256) {
        float v = row[k];
        float e = (v == -INFINITY) ? 0.0f : __expf(v - mx);
        row[k] = e;
        sum += e;
    }
    red[tid] = sum;
    __syncthreads();
    #pragma unroll
    for (int s = 128; s > 0; s >>= 1) {
        if (tid < s) red[tid] += red[tid + s];
        __syncthreads();
    }
    float inv = 1.0f / red[0];
    __syncthreads();

    size_t base = ((size_t)b * LL + ii) * LL / 2;
    for (int kp = tid; kp < LL / 2; kp += 256) {
        float v0 = row[2 * kp] * inv;
        float v1 = row[2 * kp + 1] * inv;
        uint32_t hi = pack_bf16_hi(v0, v1);
        g_Pbh32[base + kp] = hi;
        g_Pbl32[base + kp] = pack_bf16_lo(v0, v1, hi);
    }
}

// ---------------------------------------------------------------------------
// Kernel 4a: shift GEMM stage 1 (tensor cores, K-split 4, partials).
// ---------------------------------------------------------------------------
#define SH_PH 0
#define SH_PL 8192
#define SH_FH 16384
#define SH_FL 24576

__global__ __launch_bounds__(256) void k_shift1() {
    __shared__ char smem[32768];
    uint32_t sbase = smem_u32(smem);

    int i0 = blockIdx.x * 64;
    int ks = blockIdx.y;
    int b  = blockIdx.z;
    if (i0 >= g_nflag) return;

    int tid  = threadIdx.x;
    int wid  = tid >> 5;
    int lane = tid & 31;
    int wm = (wid >> 1) * 16;
    int wn = (wid & 1) * 32;
    int j  = lane & 7;
    int g  = lane >> 3;

    float acc[4][4];
    #pragma unroll
    for (int t = 0; t < 4; t++)
        #pragma unroll
        for (int q = 0; q < 4; q++) acc[t][q] = 0.0f;

    for (int kc = 0; kc < 16; kc++) {
        int kb0 = ks * 1024 + kc * 64;
        __syncthreads();
        #pragma unroll
        for (int i = 0; i < 8; i++) {
            int e  = tid + i * 256;
            int r  = e >> 5;
            int cp = e & 31;
            size_t pidx = ((size_t)(b * LL + i0 + r) * LL + kb0) / 2 + cp;
            size_t fidx = ((size_t)(b * 64 + r) * LL + kb0) / 2 + cp;
            uint32_t off = SW128((uint32_t)(r * 128 + cp * 4));
            *(uint32_t*)(smem + SH_PH + off) = g_Pbh32[pidx];
            *(uint32_t*)(smem + SH_PL + off) = g_Pbl32[pidx];
            *(uint32_t*)(smem + SH_FH + off) = g_Fbh32[fidx];
            *(uint32_t*)(smem + SH_FL + off) = g_Fbl32[fidx];
        }
        __syncthreads();

        #pragma unroll
        for (int ksub = 0; ksub < 4; ksub++) {
            int kb = ksub * 32;
            uint32_t a_hi[4], a_lo[4], b_hi[2][4], b_lo[2][4];
            {
                uint32_t row = wm + (g & 1) * 8 + j;
                uint32_t off = SW128(row * 128 + kb + (g >> 1) * 16);
                ldsm_x4(a_hi, sbase + SH_PH + off);
                ldsm_x4(a_lo, sbase + SH_PL + off);
            }
            #pragma unroll
            for (int tp = 0; tp < 2; tp++) {
                uint32_t row = wn + tp * 16 + (g >> 1) * 8 + j;
                uint32_t off = SW128(row * 128 + kb + (g & 1) * 16);
                ldsm_x4(b_hi[tp], sbase + SH_FH + off);
                ldsm_x4(b_lo[tp], sbase + SH_FL + off);
            }
            #pragma unroll
            for (int pass = 0; pass < 3; pass++) {
                #pragma unroll
                for (int t = 0; t < 4; t++) {
                    const uint32_t* ap = (pass == 2) ? a_lo : a_hi;
                    const uint32_t* bp = (pass == 1)
                        ? &b_lo[t >> 1][(t & 1) * 2]
                        : &b_hi[t >> 1][(t & 1) * 2];
                    mma_bf16(acc[t], ap, bp);
                }
            }
        }
    }

    float* part = g_part + (size_t)(b * 4 + ks) * LL * 64;
    #pragma unroll
    for (int t = 0; t < 4; t++) {
        #pragma unroll
        for (int q = 0; q < 4; q++) {
            int row = wm + (lane >> 2) + ((q >= 2) ? 8 : 0);
            int ch  = wn + t * 8 + (lane & 3) * 2 + (q & 1);
            part[(size_t)(i0 + row) * 64 + ch] = acc[t][q];
        }
    }
}

// ---------------------------------------------------------------------------
// Kernel 4b: shift stage 2 — sum 4 K-split partials, scatter to out.
// ---------------------------------------------------------------------------
__global__ __launch_bounds__(256) void k_shift2(float* __restrict__ out) {
    int idx = blockIdx.x * 256 + threadIdx.x;
    int ch = idx & 63;
    int ii = (idx >> 6) & (LL - 1);
    int b  = idx >> 18;
    if (ii >= g_nflag) return;
    float s = 0.0f;
    #pragma unroll
    for (int ks = 0; ks < 4; ks++)
        s += g_part[(size_t)(b * 4 + ks) * LL * 64 + (size_t)ii * 64 + ch];
    int l = g_list[ii];
    out[((size_t)b * 192 + 128 + ch) * LL + l] = s;
}

// ---------------------------------------------------------------------------
extern "C" void kernel_launch(void* const* d_in, const int* in_sizes, int n_in,
                              void* d_out, int out_size) {
    const float* x    = (const float*)d_in[0];   // (2,128,64,64)
    const float* mask = (const float*)d_in[1];   // (1,1,64,64)
    float* out = (float*)d_out;                  // (2,192,64,64)

    {
        int total = BB * 192 * LL;
        k_init_out<<<(total + 255) / 256, 256>>>(x, out);
    }
    {
        int total = BB * 64 * (LL / 2);
        k_fconv<<<(total + 255) / 256, 256>>>(x);
    }
    {
        int total = BB * LL;
        k_prep<<<(total + 255) / 256, 256>>>(x, mask);
    }
    {
        cudaFuncSetAttribute(k_gemm_mma, cudaFuncAttributeMaxDynamicSharedMemorySize, SM_DYN);
        dim3 grid(LL / 128, LL / 128, BB);
        k_gemm_mma<<<grid, 256, SM_DYN>>>();
    }
    k_compact<<<1, 256>>>();
    {
        dim3 grid(LL, BB);
        k_softmax<<<grid, 256>>>();
    }
    {
        dim3 grid(LL / 64, 4, BB);
        k_shift1<<<grid, 256>>>();
    }
    {
        int total = BB * LL * 64;
        k_shift2<<<total / 256, 256>>>(out);
    }
}

// round 17
// speedup vs baseline: 1.4875x; 1.1716x over previous
#include <cuda_runtime.h>
#include <cuda_bf16.h>
#include <cuda_fp16.h>
#include <cstdint>
#include <math.h>

// Problem constants (fixed shapes from setup_inputs)
#define BB 2
#define CC 64
#define LL 4096   // H*W = 64*64

// Scratch
__device__ __half   g_S[(size_t)BB * LL * LL];          // score matrix, fp16, 64 MiB
__device__ uint32_t g_Pb32[(size_t)BB * LL * LL / 2];   // attn rows bf16 (packed pairs)
__device__ uint32_t g_Fb32[(size_t)BB * 64 * LL / 2];   // former bf16
__device__ uint32_t g_XTh[(size_t)BB * LL * 32];        // latter^T bf16 hi  [b][l][ch pairs]
__device__ uint32_t g_XTl[(size_t)BB * LL * 32];        // latter^T bf16 lo
__device__ uint32_t g_XNh[(size_t)BB * LL * 32];        // normalized latter^T bf16 hi
__device__ uint32_t g_XNl[(size_t)BB * LL * 32];        // normalized latter^T bf16 lo
__device__ float    g_part[(size_t)BB * 4 * LL * 64];   // K-split partials, 8 MiB
__device__ int      g_flag[LL];
__device__ int      g_list[LL];
__device__ int      g_nflag;

// ---------------------------------------------------------------------------
// helpers
// ---------------------------------------------------------------------------
__device__ __forceinline__ uint32_t smem_u32(const void* p) {
    uint32_t a;
    asm("{ .reg .u64 t; cvta.to.shared.u64 t, %1; cvt.u32.u64 %0, t; }"
        : "=r"(a) : "l"(p));
    return a;
}
__device__ __forceinline__ void ldsm_x4(uint32_t* r, uint32_t addr) {
    asm volatile("ldmatrix.sync.aligned.m8n8.x4.shared.b16 {%0,%1,%2,%3}, [%4];"
                 : "=r"(r[0]), "=r"(r[1]), "=r"(r[2]), "=r"(r[3]) : "r"(addr));
}
__device__ __forceinline__ void mma_bf16(float* d, const uint32_t* a, const uint32_t* b) {
    asm volatile(
        "mma.sync.aligned.m16n8k16.row.col.f32.bf16.bf16.f32 "
        "{%0,%1,%2,%3}, {%4,%5,%6,%7}, {%8,%9}, {%0,%1,%2,%3};"
        : "+f"(d[0]), "+f"(d[1]), "+f"(d[2]), "+f"(d[3])
        : "r"(a[0]), "r"(a[1]), "r"(a[2]), "r"(a[3]), "r"(b[0]), "r"(b[1]));
}
__device__ __forceinline__ void hadd2(uint32_t& d, uint32_t a) {
    asm("add.rn.f16x2 %0, %0, %1;" : "+r"(d) : "r"(a));
}
#define SW128(o) ((o) ^ (((o) >> 3) & 0x70))

__device__ __forceinline__ uint32_t pack_bf16_hi(float v0, float v1) {
    unsigned short h0 = __bfloat16_as_ushort(__float2bfloat16(v0));
    unsigned short h1 = __bfloat16_as_ushort(__float2bfloat16(v1));
    return (uint32_t)h0 | ((uint32_t)h1 << 16);
}
__device__ __forceinline__ uint32_t pack_bf16_lo(float v0, float v1, uint32_t hi) {
    float h0 = __bfloat162float(__ushort_as_bfloat16((unsigned short)(hi & 0xFFFF)));
    float h1 = __bfloat162float(__ushort_as_bfloat16((unsigned short)(hi >> 16)));
    unsigned short l0 = __bfloat16_as_ushort(__float2bfloat16(v0 - h0));
    unsigned short l1 = __bfloat16_as_ushort(__float2bfloat16(v1 - h1));
    return (uint32_t)l0 | ((uint32_t)l1 << 16);
}

// ---------------------------------------------------------------------------
// Kernel 0: copy former+latter into out channels [0,128), zero shift [128,192)
// float4 vectorized.
// ---------------------------------------------------------------------------
__global__ void k_init_out(const float4* __restrict__ x4, float4* __restrict__ out4) {
    int idx = blockIdx.x * blockDim.x + threadIdx.x;
    const int total = BB * 192 * (LL / 4);
    if (idx >= total) return;
    int b  = idx / (192 * (LL / 4));
    int r  = idx - b * (192 * (LL / 4));
    int ch = r >> 10;
    int l4 = r & 1023;
    float4 v = make_float4(0.f, 0.f, 0.f, 0.f);
    if (ch < 128) v = x4[((size_t)b * 128 + ch) * (LL / 4) + l4];
    out4[idx] = v;
}

// ---------------------------------------------------------------------------
// Kernel 0b: convert former to single bf16 plane (packed pairs)
// ---------------------------------------------------------------------------
__global__ void k_fconv(const float* __restrict__ x) {
    int p = blockIdx.x * blockDim.x + threadIdx.x;
    const int total = BB * 64 * (LL / 2);
    if (p >= total) return;
    int b   = p / (64 * (LL / 2));
    int rem = p - b * (64 * (LL / 2));
    int ch  = rem / (LL / 2);
    int cp  = rem - ch * (LL / 2);
    const float* src = x + ((size_t)(b * 128 + ch)) * LL + cp * 2;
    g_Fb32[p] = pack_bf16_hi(src[0], src[1]);
}

// ---------------------------------------------------------------------------
// Kernel 1: per-(b,k): latter column -> XT hi/lo planes (raw + normalized),
// plus flags. ALL bf16 conversion happens here, once.
// ---------------------------------------------------------------------------
__global__ __launch_bounds__(256) void k_prep(const float* __restrict__ x,
                                              const float* __restrict__ mask) {
    int t = blockIdx.x * blockDim.x + threadIdx.x;
    if (t >= BB * LL) return;
    int b = t >> 12;
    int k = t & (LL - 1);
    const float* lat = x + ((size_t)b * 128 + 64) * LL;
    float v[CC];
    float s = 0.0f;
    #pragma unroll
    for (int c = 0; c < CC; c++) {
        v[c] = lat[(size_t)c * LL + k];
        s += v[c] * v[c];
    }
    float invn = 1.0f / fmaxf(sqrtf(s), 1e-4f);

    size_t base = (size_t)t * 32;
    #pragma unroll
    for (int p = 0; p < 32; p++) {
        float a0 = v[2 * p], a1 = v[2 * p + 1];
        uint32_t hi = pack_bf16_hi(a0, a1);
        g_XTh[base + p] = hi;
        g_XTl[base + p] = pack_bf16_lo(a0, a1, hi);
        float n0 = a0 * invn, n1 = a1 * invn;
        uint32_t nhi = pack_bf16_hi(n0, n1);
        g_XNh[base + p] = nhi;
        g_XNl[base + p] = pack_bf16_lo(n0, n1, nhi);
    }
    if (t < LL) g_flag[t] = (mask[t] > 0.5f) ? 1 : 0;
}

// ---------------------------------------------------------------------------
// Kernel 2: mma.sync bf16x3 score GEMM (proven). Pure uint4 fills; fp16 S.
// ---------------------------------------------------------------------------
#define SM_AH 0
#define SM_AL 16384
#define SM_BH 32768
#define SM_BL 49152
#define SM_DYN 65536

__global__ __launch_bounds__(256) void k_gemm_mma() {
    extern __shared__ char smem[];
    uint32_t sbase = smem_u32(smem);
    int tid  = threadIdx.x;
    int n0 = blockIdx.x * 128;
    int m0 = blockIdx.y * 128;
    int b  = blockIdx.z;

    #pragma unroll
    for (int it = 0; it < 4; it++) {
        int task = tid + it * 256;
        int row = task >> 3, sec = task & 7;
        uint32_t off = SW128((uint32_t)(row * 128 + sec * 16));
        *(uint4*)(smem + SM_AH + off) = ((const uint4*)g_XTh)[((size_t)b * LL + m0 + row) * 8 + sec];
        *(uint4*)(smem + SM_AL + off) = ((const uint4*)g_XTl)[((size_t)b * LL + m0 + row) * 8 + sec];
        *(uint4*)(smem + SM_BH + off) = ((const uint4*)g_XNh)[((size_t)b * LL + n0 + row) * 8 + sec];
        *(uint4*)(smem + SM_BL + off) = ((const uint4*)g_XNl)[((size_t)b * LL + n0 + row) * 8 + sec];
    }
    __syncthreads();

    int wid  = tid >> 5;
    int lane = tid & 31;
    int wm = (wid & 3) * 32;
    int wn = (wid >> 2) * 64;
    int j  = lane & 7;
    int g  = lane >> 3;

    float acc[2][8][4];
    #pragma unroll
    for (int mi = 0; mi < 2; mi++)
        #pragma unroll
        for (int t = 0; t < 8; t++)
            #pragma unroll
            for (int q = 0; q < 4; q++) acc[mi][t][q] = 0.0f;

    #pragma unroll
    for (int kc = 0; kc < 4; kc++) {
        int kb = kc * 32;

        uint32_t a_hi[2][4], a_lo[2][4], b_hi[4][4], b_lo[4][4];
        #pragma unroll
        for (int mi = 0; mi < 2; mi++) {
            uint32_t row = wm + mi * 16 + (g & 1) * 8 + j;
            uint32_t kby = kb + (g >> 1) * 16;
            uint32_t off = SW128(row * 128 + kby);
            ldsm_x4(a_hi[mi], sbase + SM_AH + off);
            ldsm_x4(a_lo[mi], sbase + SM_AL + off);
        }
        #pragma unroll
        for (int tp = 0; tp < 4; tp++) {
            uint32_t row = wn + tp * 16 + (g >> 1) * 8 + j;
            uint32_t kby = kb + (g & 1) * 16;
            uint32_t off = SW128(row * 128 + kby);
            ldsm_x4(b_hi[tp], sbase + SM_BH + off);
            ldsm_x4(b_lo[tp], sbase + SM_BL + off);
        }

        #pragma unroll
        for (int mi = 0; mi < 2; mi++)
            #pragma unroll
            for (int t = 0; t < 8; t++) {
                const uint32_t* bh = &b_hi[t >> 1][(t & 1) * 2];
                const uint32_t* bl = &b_lo[t >> 1][(t & 1) * 2];
                mma_bf16(acc[mi][t], a_hi[mi], bh);
                mma_bf16(acc[mi][t], a_hi[mi], bl);
                mma_bf16(acc[mi][t], a_lo[mi], bh);
            }
    }

    __half* Sp = g_S + (size_t)b * LL * LL;
    #pragma unroll
    for (int t = 0; t < 8; t++) {
        int n = wn + t * 8 + (lane & 3) * 2;
        #pragma unroll
        for (int mi = 0; mi < 2; mi++) {
            int r0 = m0 + wm + mi * 16 + (lane >> 2);
            __half2 p0 = __floats2half2_rn(acc[mi][t][0], acc[mi][t][1]);
            __half2 p1 = __floats2half2_rn(acc[mi][t][2], acc[mi][t][3]);
            *(__half2*)&Sp[(size_t)r0 * LL + n0 + n] = p0;
            *(__half2*)&Sp[(size_t)(r0 + 8) * LL + n0 + n] = p1;
        }
    }
}

// ---------------------------------------------------------------------------
// Kernel 1b: deterministic compaction (warp-shfl scan, 2 barriers)
// ---------------------------------------------------------------------------
__global__ void k_compact() {
    __shared__ int wsum[8];
    int t = threadIdx.x;
    int lane = t & 31;
    int warp = t >> 5;
    int base_l = t * 16;
    int fl[16];
    #pragma unroll
    for (int q = 0; q < 4; q++) {
        int4 v = *(const int4*)&g_flag[base_l + q * 4];
        fl[q * 4 + 0] = v.x; fl[q * 4 + 1] = v.y;
        fl[q * 4 + 2] = v.z; fl[q * 4 + 3] = v.w;
    }
    int c = 0;
    #pragma unroll
    for (int j = 0; j < 16; j++) c += fl[j];
    int inc = c;
    #pragma unroll
    for (int off = 1; off < 32; off <<= 1) {
        int v = __shfl_up_sync(0xFFFFFFFFu, inc, off);
        if (lane >= off) inc += v;
    }
    if (lane == 31) wsum[warp] = inc;
    __syncthreads();
    if (t == 0) {
        int run = 0;
        #pragma unroll
        for (int i = 0; i < 8; i++) { int v = wsum[i]; wsum[i] = run; run += v; }
        g_nflag = run;
    }
    __syncthreads();
    int posF = wsum[warp] + inc - c;
    #pragma unroll
    for (int j = 0; j < 16; j++) {
        int l = base_l + j;
        if (fl[j]) g_list[posF++] = l;
    }
}

// ---------------------------------------------------------------------------
// Kernel 3: per flagged row: 9-point fused gather (fp16 S, half2 accumulate
// with funnel-shift alignment) + masked softmax (fp32 exp); write attn row
// as single bf16 plane.
// ---------------------------------------------------------------------------
__global__ __launch_bounds__(256) void k_softmax() {
    int ii = blockIdx.x;
    if (ii >= g_nflag) return;
    int l = g_list[ii];
    int b = blockIdx.y;

    __shared__ float row[LL];
    __shared__ float red[256];

    const __half* S = g_S + (size_t)b * LL * LL;
    int tid = threadIdx.x;

    int hl = l >> 6, wl = l & 63;
    int ml = (wl << 6) | hl;

    const __half* rp[3][3];
    bool rv[3][3];
    #pragma unroll
    for (int ei = 0; ei < 3; ei++) {
        int m2 = ml + ei - 1;
        bool v = (m2 >= 0 && m2 < LL);
        int l2v = v ? (((m2 & 63) << 6) | (m2 >> 6)) : 0;
        #pragma unroll
        for (int di = 0; di < 3; di++) {
            int r = l2v + di - 1;
            bool ok = v && (r >= 0 && r < LL);
            rv[ei][di] = ok;
            rp[ei][di] = ok ? (S + (size_t)r * LL) : S;
        }
    }

    float mx = -INFINITY;
    for (int idx = tid; idx < LL / 4; idx += 256) {
        int k0 = idx * 4;
        int h  = k0 >> 6;
        int w0 = k0 & 63;
        uint32_t a01 = 0, a23 = 0;          // half2 accumulators
        float e0 = 0.f, e1 = 0.f, e2 = 0.f, e3 = 0.f;  // edge terms (fp32)

        #pragma unroll
        for (int ei = 0; ei < 3; ei++) {
            int hh = h + ei - 1;
            if (hh >= 0 && hh < 64) {
                int k2 = (hh << 6) | w0;
                #pragma unroll
                for (int di = 0; di < 3; di++) {
                    if (!rv[ei][di]) continue;
                    const __half* rw = rp[ei][di];
                    uint2 raw = *(const uint2*)&rw[k2];
                    if (di == 1) {
                        hadd2(a01, raw.x);
                        hadd2(a23, raw.y);
                    } else if (di == 0) {
                        uint32_t vl = (k2 >= 1) ? (uint32_t)*(const unsigned short*)&rw[k2 - 1] : 0u;
                        hadd2(a01, (raw.x << 16) | vl);
                        hadd2(a23, __funnelshift_l(raw.x, raw.y, 16));
                    } else {
                        uint32_t vr = (k2 + 4 < LL) ? (uint32_t)*(const unsigned short*)&rw[k2 + 4] : 0u;
                        hadd2(a01, __funnelshift_l(raw.x, raw.y, 16));
                        hadd2(a23, (vr << 16) | (raw.y >> 16));
                    }
                }
            } else {
                bool neg = (hh < 0);
                float* accp[4] = {&e0, &e1, &e2, &e3};
                #pragma unroll
                for (int jj = 0; jj < 4; jj++) {
                    int w = w0 + jj;
                    int k2; bool kv;
                    if (neg) { k2 = 4032 + (w - 1); kv = (w >= 1); }
                    else     { k2 = w + 1;          kv = (w <= 62); }
                    if (!kv) continue;
                    #pragma unroll
                    for (int di = 0; di < 3; di++) {
                        int c = k2 + di - 1;
                        if (rv[ei][di] && c >= 0 && c < LL)
                            *accp[jj] += __half2float(rp[ei][di][c]);
                    }
                }
            }
        }

        float2 f01 = __half22float2(*(__half2*)&a01);
        float2 f23 = __half22float2(*(__half2*)&a23);
        int4 fl = *(const int4*)&g_flag[k0];
        float v0 = fl.x ? -INFINITY : (f01.x + e0);
        float v1 = fl.y ? -INFINITY : (f01.y + e1);
        float v2 = fl.z ? -INFINITY : (f23.x + e2);
        float v3 = fl.w ? -INFINITY : (f23.y + e3);
        *(float4*)&row[k0] = make_float4(v0, v1, v2, v3);
        mx = fmaxf(mx, fmaxf(fmaxf(v0, v1), fmaxf(v2, v3)));
    }

    red[tid] = mx;
    __syncthreads();
    #pragma unroll
    for (int s = 128; s > 0; s >>= 1) {
        if (tid < s) red[tid] = fmaxf(red[tid], red[tid + s]);
        __syncthreads();
    }
    mx = red[0];
    __syncthreads();

    float sum = 0.0f;
    for (int k = tid; k < LL; k += 256) {
        float v = row[k];
        float e = (v == -INFINITY) ? 0.0f : __expf(v - mx);
        row[k] = e;
        sum += e;
    }
    red[tid] = sum;
    __syncthreads();
    #pragma unroll
    for (int s = 128; s > 0; s >>= 1) {
        if (tid < s) red[tid] += red[tid + s];
        __syncthreads();
    }
    float inv = 1.0f / red[0];
    __syncthreads();

    size_t base = ((size_t)b * LL + ii) * LL / 2;
    for (int kp = tid; kp < LL / 2; kp += 256) {
        g_Pb32[base + kp] = pack_bf16_hi(row[2 * kp] * inv, row[2 * kp + 1] * inv);
    }
}

// ---------------------------------------------------------------------------
// Kernel 4a: shift GEMM stage 1 — SINGLE-PASS bf16 (P and F single planes).
// ---------------------------------------------------------------------------
#define SH_P 0
#define SH_F 8192

__global__ __launch_bounds__(256) void k_shift1() {
    __shared__ char smem[16384];
    uint32_t sbase = smem_u32(smem);

    int i0 = blockIdx.x * 64;
    int ks = blockIdx.y;
    int b  = blockIdx.z;
    if (i0 >= g_nflag) return;

    int tid  = threadIdx.x;
    int wid  = tid >> 5;
    int lane = tid & 31;
    int wm = (wid >> 1) * 16;
    int wn = (wid & 1) * 32;
    int j  = lane & 7;
    int g  = lane >> 3;

    float acc[4][4];
    #pragma unroll
    for (int t = 0; t < 4; t++)
        #pragma unroll
        for (int q = 0; q < 4; q++) acc[t][q] = 0.0f;

    for (int kc = 0; kc < 16; kc++) {
        int kb0 = ks * 1024 + kc * 64;
        __syncthreads();
        // fill: 2 planes x 64 rows x 8 sectors (16B) = 1024 tasks, 4/thread
        #pragma unroll
        for (int i = 0; i < 4; i++) {
            int task = tid + i * 256;
            int row  = (task >> 3) & 63;
            int sec  = task & 7;
            int pl   = task >> 9;     // 0 = P, 1 = F
            uint32_t off = SW128((uint32_t)(row * 128 + sec * 16));
            if (pl == 0) {
                size_t gi = ((size_t)(b * LL + i0 + row) * LL + kb0) / 8 + sec;
                *(uint4*)(smem + SH_P + off) = ((const uint4*)g_Pb32)[gi];
            } else {
                size_t gi = ((size_t)(b * 64 + row) * LL + kb0) / 8 + sec;
                *(uint4*)(smem + SH_F + off) = ((const uint4*)g_Fb32)[gi];
            }
        }
        __syncthreads();

        #pragma unroll
        for (int ksub = 0; ksub < 4; ksub++) {
            int kb = ksub * 32;
            uint32_t a_f[4], b_f[2][4];
            {
                uint32_t row = wm + (g & 1) * 8 + j;
                uint32_t off = SW128(row * 128 + kb + (g >> 1) * 16);
                ldsm_x4(a_f, sbase + SH_P + off);
            }
            #pragma unroll
            for (int tp = 0; tp < 2; tp++) {
                uint32_t row = wn + tp * 16 + (g >> 1) * 8 + j;
                uint32_t off = SW128(row * 128 + kb + (g & 1) * 16);
                ldsm_x4(b_f[tp], sbase + SH_F + off);
            }
            #pragma unroll
            for (int t = 0; t < 4; t++)
                mma_bf16(acc[t], a_f, &b_f[t >> 1][(t & 1) * 2]);
        }
    }

    float* part = g_part + (size_t)(b * 4 + ks) * LL * 64;
    #pragma unroll
    for (int t = 0; t < 4; t++) {
        #pragma unroll
        for (int q = 0; q < 4; q++) {
            int row = wm + (lane >> 2) + ((q >= 2) ? 8 : 0);
            int ch  = wn + t * 8 + (lane & 3) * 2 + (q & 1);
            part[(size_t)(i0 + row) * 64 + ch] = acc[t][q];
        }
    }
}

// ---------------------------------------------------------------------------
// Kernel 4b: shift stage 2 — sum 4 K-split partials, scatter to out.
// ---------------------------------------------------------------------------
__global__ __launch_bounds__(256) void k_shift2(float* __restrict__ out) {
    int idx = blockIdx.x * 256 + threadIdx.x;
    int ch = idx & 63;
    int ii = (idx >> 6) & (LL - 1);
    int b  = idx >> 18;
    if (ii >= g_nflag) return;
    float s = 0.0f;
    #pragma unroll
    for (int ks = 0; ks < 4; ks++)
        s += g_part[(size_t)(b * 4 + ks) * LL * 64 + (size_t)ii * 64 + ch];
    int l = g_list[ii];
    out[((size_t)b * 192 + 128 + ch) * LL + l] = s;
}

// ---------------------------------------------------------------------------
extern "C" void kernel_launch(void* const* d_in, const int* in_sizes, int n_in,
                              void* d_out, int out_size) {
    const float* x    = (const float*)d_in[0];   // (2,128,64,64)
    const float* mask = (const float*)d_in[1];   // (1,1,64,64)
    float* out = (float*)d_out;                  // (2,192,64,64)

    {
        int total = BB * 192 * (LL / 4);
        k_init_out<<<(total + 255) / 256, 256>>>((const float4*)x, (float4*)out);
    }
    {
        int total = BB * 64 * (LL / 2);
        k_fconv<<<(total + 255) / 256, 256>>>(x);
    }
    {
        int total = BB * LL;
        k_prep<<<(total + 255) / 256, 256>>>(x, mask);
    }
    {
        cudaFuncSetAttribute(k_gemm_mma, cudaFuncAttributeMaxDynamicSharedMemorySize, SM_DYN);
        dim3 grid(LL / 128, LL / 128, BB);
        k_gemm_mma<<<grid, 256, SM_DYN>>>();
    }
    k_compact<<<1, 256>>>();
    {
        dim3 grid(LL, BB);
        k_softmax<<<grid, 256>>>();
    }
    {
        dim3 grid(LL / 64, 4, BB);
        k_shift1<<<grid, 256>>>();
    }
    {
        int total = BB * LL * 64;
        k_shift2<<<total / 256, 256>>>(out);
    }
}